// round 16
// baseline (speedup 1.0000x reference)
#include <cuda_runtime.h>

// CTC forward loss — forward/backward split + TWO-CHAIN INTERLEAVE per warp.
// B=128, T=1024, C=128 (blank=127), L=128, S=257.
//
// One CTA (128 threads = 4 warps) per PAIR of batch elements (grid = B/2):
//   warp 0: two interleaved FORWARD DPs (batches 2b, 2b+1), rows 0..559.
//   warp 1: two interleaved BACKWARD DPs, rows 1023..560.
//   warp 2: softmax log-normalizer, full batch 2b.
//   warp 3: softmax log-normalizer, full batch 2b+1.
// The two chains in a warp are independent; ptxas interleaves their
// instructions inside each unrolled block, filling dependency bubbles.
// Per-chain DP machinery is identical to the round-15 kernel.

#define T_   1024
#define C_   128
#define L_   128
#define EPS_ 1e-7f
#define CEPS_ (128.0f * 1e-7f)
#define FULL 0xffffffffu
#define LN2  0.6931471805599453f

// ---------------- forward chain state ----------------
struct FS {
    float gbr[8][4];
    float pbr[8];
    float a0, a1, a2, a3, a4, a5, a6, a7, a256;
    float sc_pm, sc_pm_nx, pm1;
    float cq0, cq1, cq2, cq3, cpb;
    float sk0, sk1, sk2, sk3;
    int   e, e_up_save;
    int   cls0, cls1, cls2, cls3;
    const float* row;
};

__device__ __forceinline__ void load_labels(int& cls0, int& cls1, int& cls2,
                                            int& cls3, float& sk0, float& sk1,
                                            float& sk2, float& sk3,
                                            const int* yt, int lane)
{
    int4 c4 = *(const int4*)(yt + 4 * lane);
    cls0 = c4.x; cls1 = c4.y; cls2 = c4.z; cls3 = c4.w;
    int clsm1 = __shfl_up_sync(FULL, cls3, 1);
    sk0 = (lane > 0 && cls0 != clsm1) ? 1.f : 0.f;
    sk1 = (cls1 != cls0) ? 1.f : 0.f;
    sk2 = (cls2 != cls1) ? 1.f : 0.f;
    sk3 = (cls3 != cls2) ? 1.f : 0.f;
}

__device__ __forceinline__ void finit(FS& S, const float* row,
                                      const int* yt, int lane)
{
    S.row = row;
    load_labels(S.cls0, S.cls1, S.cls2, S.cls3,
                S.sk0, S.sk1, S.sk2, S.sk3, yt, lane);
#pragma unroll
    for (int j = 0; j < 8; j++) {
        const float* r = row + (size_t)j * C_;
        S.gbr[j][0] = r[S.cls0]; S.gbr[j][1] = r[S.cls1];
        S.gbr[j][2] = r[S.cls2]; S.gbr[j][3] = r[S.cls3];
        S.pbr[j]    = r[C_ - 1];
    }
    S.a0 = S.a1 = S.a2 = S.a3 = S.a4 = S.a5 = S.a6 = S.a7 = S.a256 = 0.f;
    S.e = 0; S.e_up_save = 0;
    S.sc_pm = (lane == 0) ? 0.f : 1.f;
    S.sc_pm_nx = S.sc_pm;
    S.pm1 = 0.f;
    // t = 0: init states 0 (blank) and 1 (first label); refill slot 0
    const float q00 = S.gbr[0][0] + EPS_;
    const float pb0 = S.pbr[0] + EPS_;
    if (lane == 0) { S.a0 = pb0; S.a1 = q00; }
    const float* r8 = row + (size_t)8 * C_;
    S.gbr[0][0] = r8[S.cls0]; S.gbr[0][1] = r8[S.cls1];
    S.gbr[0][2] = r8[S.cls2]; S.gbr[0][3] = r8[S.cls3];
    S.pbr[0]    = r8[C_ - 1];
    // prep operands for t = 1
    S.cq0 = S.gbr[1][0] + EPS_; S.cq1 = S.gbr[1][1] + EPS_;
    S.cq2 = S.gbr[1][2] + EPS_; S.cq3 = S.gbr[1][3] + EPS_;
    S.cpb = S.pbr[1] + EPS_;
}

template<int PH, int RS, int RF, int PREP>
__device__ __forceinline__ void fstep(FS& S, int t, int lane)
{
    const float n7 = fmaf(S.sk3, S.a5, S.a7 + S.a6) * S.cq3;
    const float a7s = __shfl_up_sync(FULL, n7, 1);
    const float n8 = (S.a256 + S.a7) * S.cpb;
    const float n0 = (S.a0 + S.pm1) * S.cpb;
    const float n1 = fmaf(S.sk0, S.pm1, S.a1 + S.a0) * S.cq0;
    const float n2 = (S.a2 + S.a1) * S.cpb;
    const float n3 = fmaf(S.sk1, S.a1, S.a3 + S.a2) * S.cq1;
    const float n4 = (S.a4 + S.a3) * S.cpb;
    const float n5 = fmaf(S.sk2, S.a3, S.a5 + S.a4) * S.cq2;
    const float n6 = (S.a6 + S.a5) * S.cpb;
    if (RF) {
        const float* r8 = S.row + (size_t)(t + 8) * C_;
        S.gbr[PH][0] = r8[S.cls0]; S.gbr[PH][1] = r8[S.cls1];
        S.gbr[PH][2] = r8[S.cls2]; S.gbr[PH][3] = r8[S.cls3];
        S.pbr[PH]    = r8[C_ - 1];
    }
    S.a0 = n0; S.a1 = n1; S.a2 = n2; S.a3 = n3;
    S.a4 = n4; S.a5 = n5; S.a6 = n6; S.a7 = n7; S.a256 = n8;
    float sckq = 1.f;
    if (RS) {
        float m = fmaxf(fmaxf(fmaxf(n0, n1), fmaxf(n2, n3)),
                        fmaxf(fmaxf(n4, n5), fmaxf(n6, n7)));
        m = fmaxf(m, n8);
        const bool has = (m > 0.f);
        const int k = has ? ((__float_as_int(m) >> 23) - 127) : 0;
        sckq = __int_as_float((127 - k) << 23);
        S.e = has ? (S.e + k) : S.e_up_save;
        S.e_up_save = __shfl_up_sync(FULL, S.e, 1);
        const int bexp = min(max(S.e_up_save - S.e + 127, 0), 254);
        S.sc_pm_nx = (lane == 0) ? 0.f : __int_as_float(bexp << 23);
    }
    S.pm1 = a7s * S.sc_pm;      // OLD sc_pm: scale frame of step t
    if (RS) S.sc_pm = S.sc_pm_nx;
    if (PREP) {
        const int NP = (PH + 1) & 7;
        S.cq0 = S.gbr[NP][0] + EPS_; S.cq1 = S.gbr[NP][1] + EPS_;
        S.cq2 = S.gbr[NP][2] + EPS_; S.cq3 = S.gbr[NP][3] + EPS_;
        S.cpb = S.pbr[NP] + EPS_;
        if (RS) { S.cq0 *= sckq; S.cq1 *= sckq; S.cq2 *= sckq;
                  S.cq3 *= sckq; S.cpb *= sckq; }
    }
}

// ---------------- backward chain state ----------------
struct BS {
    float dbr[8][4];
    float dpr[8];
    float b0, b1, b2, b3, b4, b5, b6, b7, b256;
    float sc_cm;
    float dq0, dq1, dq2, dq3, dpb, dqs1, dqs2, dqs3, c256, comb;
    float sk0, sk1, sk2, sk3;
    int   eb, e_dn_save;
    int   cls0, cls1, cls2, cls3;
    const float* row;
};

__device__ __forceinline__ void binit(BS& S, const float* row,
                                      const int* yt, int lane)
{
    S.row = row;
    load_labels(S.cls0, S.cls1, S.cls2, S.cls3,
                S.sk0, S.sk1, S.sk2, S.sk3, yt, lane);
#pragma unroll
    for (int j = 0; j < 8; j++) {
        const float* r = row + (size_t)(1023 - j) * C_;
        S.dbr[j][0] = r[S.cls0]; S.dbr[j][1] = r[S.cls1];
        S.dbr[j][2] = r[S.cls2]; S.dbr[j][3] = r[S.cls3];
        S.dpr[j]    = r[C_ - 1];
    }
    S.b0 = S.b1 = S.b2 = S.b3 = S.b4 = S.b5 = S.b6 = 0.f;
    S.b7   = (lane == 31) ? 1.f : 0.f;   // beta^_1023[255]
    S.b256 = (lane == 31) ? 1.f : 0.f;   // beta^_1023[256]
    S.eb = 0; S.e_dn_save = 0; S.sc_cm = 1.f;
    S.dq0 = S.dbr[0][0] + EPS_; S.dq1 = S.dbr[0][1] + EPS_;
    S.dq2 = S.dbr[0][2] + EPS_; S.dq3 = S.dbr[0][3] + EPS_;
    S.dpb = S.dpr[0] + EPS_;
    S.dqs1 = S.sk1 * S.dq1; S.dqs2 = S.sk2 * S.dq2; S.dqs3 = S.sk3 * S.dq3;
    const float gcomb = fmaf(S.sk0 * S.dq0, S.b1, S.dpb * S.b0);  // = 0
    S.c256 = S.dpb * S.b256;
    const float gsh = __shfl_down_sync(FULL, gcomb, 1);
    S.comb = (lane == 31) ? S.c256 : gsh * S.sc_cm;
}

template<int SL, int RS, int RF, int PREP>
__device__ __forceinline__ void bstep(BS& S, int u, int lane)
{
    const float b0n = fmaf(S.dq0, S.b1, S.dpb * S.b0);
    const float b1n = fmaf(S.dqs1, S.b3, fmaf(S.dpb, S.b2, S.dq0 * S.b1));
    const float b2n = fmaf(S.dq1, S.b3, S.dpb * S.b2);
    const float b3n = fmaf(S.dqs2, S.b5, fmaf(S.dpb, S.b4, S.dq1 * S.b3));
    const float b4n = fmaf(S.dq2, S.b5, S.dpb * S.b4);
    const float b5n = fmaf(S.dqs3, S.b7, fmaf(S.dpb, S.b6, S.dq2 * S.b5));
    const float b6n = fmaf(S.dq3, S.b7, S.dpb * S.b6);
    const float b7n = fmaf(S.dq3, S.b7, S.comb);
    if (RF) {
        const float* r8 = S.row + (size_t)(1015 - u) * C_;
        S.dbr[SL][0] = r8[S.cls0]; S.dbr[SL][1] = r8[S.cls1];
        S.dbr[SL][2] = r8[S.cls2]; S.dbr[SL][3] = r8[S.cls3];
        S.dpr[SL]    = r8[C_ - 1];
    }
    S.b0 = b0n; S.b1 = b1n; S.b2 = b2n; S.b3 = b3n;
    S.b4 = b4n; S.b5 = b5n; S.b6 = b6n; S.b7 = b7n; S.b256 = S.c256;
    float sckq = 1.f;
    if (RS) {
        float m = fmaxf(fmaxf(fmaxf(b0n, b1n), fmaxf(b2n, b3n)),
                        fmaxf(fmaxf(b4n, b5n), fmaxf(b6n, b7n)));
        m = fmaxf(m, S.b256);
        const bool has = (m > 0.f);
        const int k = has ? ((__float_as_int(m) >> 23) - 127) : 0;
        sckq = __int_as_float((127 - k) << 23);
        S.eb = has ? (S.eb + k) : S.e_dn_save;
        S.e_dn_save = __shfl_down_sync(FULL, S.eb, 1);
        const int bexp = min(max(S.e_dn_save - S.eb + 127, 0), 254);
        S.sc_cm = __int_as_float(bexp << 23);
    }
    if (PREP) {
        const int NP = (SL + 1) & 7;
        S.dq0 = S.dbr[NP][0] + EPS_; S.dq1 = S.dbr[NP][1] + EPS_;
        S.dq2 = S.dbr[NP][2] + EPS_; S.dq3 = S.dbr[NP][3] + EPS_;
        S.dpb = S.dpr[NP] + EPS_;
        if (RS) { S.dq0 *= sckq; S.dq1 *= sckq; S.dq2 *= sckq;
                  S.dq3 *= sckq; S.dpb *= sckq; }
        S.dqs1 = S.sk1 * S.dq1; S.dqs2 = S.sk2 * S.dq2; S.dqs3 = S.sk3 * S.dq3;
        const float gcomb = fmaf(S.sk0 * S.dq0, S.b1, S.dpb * S.b0);
        S.c256 = S.dpb * S.b256;
        const float gsh = __shfl_down_sync(FULL, gcomb, 1);
        S.comb = (lane == 31) ? S.c256 : gsh * S.sc_cm;
    }
}

// ---------------- interleaved 2-chain macros ----------------
#define F2(PH, t, RS, RF, PREP) \
    fstep<PH, RS, RF, PREP>(SA, (t), lane); \
    fstep<PH, RS, RF, PREP>(SB, (t), lane);

#define F2BLK8(tb) \
    F2(0,(tb)+0,0,1,1) F2(1,(tb)+1,0,1,1) F2(2,(tb)+2,0,1,1) \
    F2(3,(tb)+3,1,1,1) F2(4,(tb)+4,0,1,1) F2(5,(tb)+5,0,1,1) \
    F2(6,(tb)+6,0,1,1) F2(7,(tb)+7,1,1,1)
#define F2BLK8_LAST(tb) \
    F2(0,(tb)+0,0,0,1) F2(1,(tb)+1,0,0,1) F2(2,(tb)+2,0,0,1) \
    F2(3,(tb)+3,1,0,1) F2(4,(tb)+4,0,0,1) F2(5,(tb)+5,0,0,1) \
    F2(6,(tb)+6,0,0,1) F2(7,(tb)+7,0,0,0)

#define B2(SL, u, RS, RF, PREP) \
    bstep<SL, RS, RF, PREP>(BA, (u), lane); \
    bstep<SL, RS, RF, PREP>(BB, (u), lane);

#define B2BLK8(ub) \
    B2(0,(ub)+0,0,1,1) B2(1,(ub)+1,0,1,1) B2(2,(ub)+2,0,1,1) \
    B2(3,(ub)+3,1,1,1) B2(4,(ub)+4,0,1,1) B2(5,(ub)+5,0,1,1) \
    B2(6,(ub)+6,0,1,1) B2(7,(ub)+7,1,1,1)
#define B2BLK8_LAST(ub) \
    B2(0,(ub)+0,0,0,1) B2(1,(ub)+1,0,0,1) B2(2,(ub)+2,0,0,1) \
    B2(3,(ub)+3,1,0,1) B2(4,(ub)+4,0,0,1) B2(5,(ub)+5,0,0,1) \
    B2(6,(ub)+6,0,0,1) B2(7,(ub)+7,0,0,0)

// softmax log-normalizer over 512 rows starting at zrow (lane-offset applied)
__device__ __forceinline__ float zhalf(const float* __restrict__ zrow)
{
    float4 ring[4][4];
#pragma unroll
    for (int j = 0; j < 4; j++) {
        const float* p = zrow + (size_t)j * 4 * C_;
        ring[j][0] = *(const float4*)(p + 0);
        ring[j][1] = *(const float4*)(p + 4);
        ring[j][2] = *(const float4*)(p + 8);
        ring[j][3] = *(const float4*)(p + 12);
    }
    float zs = 0.f;
    for (int r8 = 0; r8 < 128; r8 += 8) {
        float zp = 1.f;
#pragma unroll
        for (int rr = 0; rr < 8; rr++) {
            const int slot = rr & 3;
            float4 v0 = ring[slot][0], v1 = ring[slot][1],
                   v2 = ring[slot][2], v3 = ring[slot][3];
            const int r = r8 + rr;
            if (r + 4 < 128) {
                const float* p = zrow + (size_t)(r + 4) * 4 * C_;
                ring[slot][0] = *(const float4*)(p + 0);
                ring[slot][1] = *(const float4*)(p + 4);
                ring[slot][2] = *(const float4*)(p + 8);
                ring[slot][3] = *(const float4*)(p + 12);
            }
            float s = ((v0.x + v0.y) + (v0.z + v0.w))
                    + ((v1.x + v1.y) + (v1.z + v1.w))
                    + ((v2.x + v2.y) + (v2.z + v2.w))
                    + ((v3.x + v3.y) + (v3.z + v3.w));
            s += __shfl_xor_sync(FULL, s, 1);
            s += __shfl_xor_sync(FULL, s, 2);
            s += __shfl_xor_sync(FULL, s, 4);
            zp *= (s + CEPS_);
        }
        zs += __logf(zp);
    }
    zs += __shfl_xor_sync(FULL, zs, 8);
    zs += __shfl_xor_sync(FULL, zs, 16);
    return zs;
}

__global__ __launch_bounds__(128, 1)
void ctc_fbi2_kernel(const int* __restrict__ y_true,
                     const float* __restrict__ y_pred,
                     float* __restrict__ out)
{
    __shared__ float sb_b[2][32 * 9];
    __shared__ int   sb_e[2][32];
    __shared__ float s_z[2];

    const int bp   = blockIdx.x;               // batch pair
    const int tid  = threadIdx.x;
    const int lane = tid & 31;
    const int wrp  = tid >> 5;
    const float* __restrict__ rowA = y_pred + (size_t)(2 * bp)     * T_ * C_;
    const float* __restrict__ rowB = y_pred + (size_t)(2 * bp + 1) * T_ * C_;
    const int* ytA = y_true + (2 * bp)     * L_;
    const int* ytB = y_true + (2 * bp + 1) * L_;

    // forward results (survive to combine)
    float faA[9]; int eA = 0;
    float faB[9]; int eB = 0;
#pragma unroll
    for (int j = 0; j < 9; j++) { faA[j] = 0.f; faB[j] = 0.f; }

    if (wrp == 0) {
        // ------------- two interleaved FORWARD chains: rows 0..559 -------
        FS SA, SB;
        finit(SA, rowA, ytA, lane);
        finit(SB, rowB, ytB, lane);
        F2(1,1,0,1,1) F2(2,2,0,1,1) F2(3,3,1,1,1) F2(4,4,0,1,1)
        F2(5,5,0,1,1) F2(6,6,0,1,1) F2(7,7,1,1,1)
        for (int tb = 8; tb < 552; tb += 8) { F2BLK8(tb) }
        F2BLK8_LAST(552)
        faA[0]=SA.a0; faA[1]=SA.a1; faA[2]=SA.a2; faA[3]=SA.a3;
        faA[4]=SA.a4; faA[5]=SA.a5; faA[6]=SA.a6; faA[7]=SA.a7;
        faA[8]=SA.a256; eA = SA.e;
        faB[0]=SB.a0; faB[1]=SB.a1; faB[2]=SB.a2; faB[3]=SB.a3;
        faB[4]=SB.a4; faB[5]=SB.a5; faB[6]=SB.a6; faB[7]=SB.a7;
        faB[8]=SB.a256; eB = SB.e;
    } else if (wrp == 1) {
        // ------------- two interleaved BACKWARD chains: rows 1023..560 ---
        BS BA, BB;
        binit(BA, rowA, ytA, lane);
        binit(BB, rowB, ytB, lane);
        for (int ub = 0; ub < 456; ub += 8) { B2BLK8(ub) }
        B2BLK8_LAST(456)
        sb_b[0][lane*9+0]=BA.b0; sb_b[0][lane*9+1]=BA.b1;
        sb_b[0][lane*9+2]=BA.b2; sb_b[0][lane*9+3]=BA.b3;
        sb_b[0][lane*9+4]=BA.b4; sb_b[0][lane*9+5]=BA.b5;
        sb_b[0][lane*9+6]=BA.b6; sb_b[0][lane*9+7]=BA.b7;
        sb_b[0][lane*9+8]=BA.b256; sb_e[0][lane]=BA.eb;
        sb_b[1][lane*9+0]=BB.b0; sb_b[1][lane*9+1]=BB.b1;
        sb_b[1][lane*9+2]=BB.b2; sb_b[1][lane*9+3]=BB.b3;
        sb_b[1][lane*9+4]=BB.b4; sb_b[1][lane*9+5]=BB.b5;
        sb_b[1][lane*9+6]=BB.b6; sb_b[1][lane*9+7]=BB.b7;
        sb_b[1][lane*9+8]=BB.b256; sb_e[1][lane]=BB.eb;
    } else if (wrp == 2) {
        const int g = lane >> 3, il = lane & 7;
        float zs = zhalf(rowA + (size_t)g * C_ + il * 16)
                 + zhalf(rowA + (size_t)(512 + g) * C_ + il * 16);
        if (lane == 0) s_z[0] = zs;
    } else {
        const int g = lane >> 3, il = lane & 7;
        float zs = zhalf(rowB + (size_t)g * C_ + il * 16)
                 + zhalf(rowB + (size_t)(512 + g) * C_ + il * 16);
        if (lane == 0) s_z[1] = zs;
    }

    __syncthreads();

    // ---------------- combine on warp 0 (both chains) ----------------
    if (wrp == 0) {
#pragma unroll
        for (int ci = 0; ci < 2; ci++) {
            const float* fa = (ci == 0) ? faA : faB;
            const int    ef = (ci == 0) ? eA : eB;
            const float* bb = &sb_b[ci][lane * 9];
            float dot = fa[0]*bb[0] + fa[1]*bb[1] + fa[2]*bb[2] + fa[3]*bb[3]
                      + fa[4]*bb[4] + fa[5]*bb[5] + fa[6]*bb[6] + fa[7]*bb[7];
            if (lane == 31) dot = fmaf(fa[8], bb[8], dot);
            const int el = ef + sb_e[ci][lane];
            int elm = (dot > 0.f) ? el : -1000000;
            elm = max(elm, __shfl_xor_sync(FULL, elm, 1));
            elm = max(elm, __shfl_xor_sync(FULL, elm, 2));
            elm = max(elm, __shfl_xor_sync(FULL, elm, 4));
            elm = max(elm, __shfl_xor_sync(FULL, elm, 8));
            elm = max(elm, __shfl_xor_sync(FULL, elm, 16));
            const int d = el - elm + 127;
            const float sc = (dot > 0.f && d >= 1) ? __int_as_float(d << 23)
                                                   : 0.f;
            float s = dot * sc;
            s += __shfl_xor_sync(FULL, s, 1);
            s += __shfl_xor_sync(FULL, s, 2);
            s += __shfl_xor_sync(FULL, s, 4);
            s += __shfl_xor_sync(FULL, s, 8);
            s += __shfl_xor_sync(FULL, s, 16);
            if (lane == 0) {
                float ll = __logf(s) + (float)elm * LN2 - s_z[ci];
                out[2 * bp + ci] = -ll;
            }
        }
    }
}

extern "C" void kernel_launch(void* const* d_in, const int* in_sizes, int n_in,
                              void* d_out, int out_size)
{
    const int* y_true;
    const float* y_pred;
    if (in_sizes[0] == 128 * L_) {            // y_true: [B,L] int32
        y_true = (const int*)d_in[0];
        y_pred = (const float*)d_in[1];
    } else {
        y_true = (const int*)d_in[1];
        y_pred = (const float*)d_in[0];
    }
    const int B = out_size;                    // [B,1] float32
    ctc_fbi2_kernel<<<B / 2, 128>>>(y_true, y_pred, (float*)d_out);
}